// round 14
// baseline (speedup 1.0000x reference)
#include <cuda_runtime.h>
#include <cuda_fp16.h>
#include <math.h>
#include <stdint.h>

// Problem constants
#define BB 128      // batch
#define TT 256      // seq len
#define DD 256      // input dim
#define HH 1024     // hidden dim
#define CC 10       // classes
#define N4 4096     // 4*HH
#define NCTA 128    // persistent CTAs (one per SM)

// Step kernel constants (R12-proven geometry)
#define NTHR 256
#define WROW 2064                       // 1024 fp16 = 2048B + 16B pad
#define S_WT 0                          // W tile: 64 x WROW = 132096
#define S_ABUF (64 * WROW)              // 132096
#define ACH_SZ 16384                    // one A chunk: 64 rows x 128 fp16 (2 subtiles)
#define STEP_SMEM (S_ABUF + 4 * ACH_SZ) // 197632

// xg MMA kernel constants (R12-proven)
#define XG_SMEM 65536
#define XCROWH 136

// ---------------------------------------------------------------------------
// Device globals
// ---------------------------------------------------------------------------
__device__ __half g_xg[(size_t)TT * BB * N4];     // [t*128+b][n=u*4+j] fp16
__device__ __half g_xA[(size_t)TT * BB * DD];     // x rows r=t*128+b fp16
__device__ __half g_Wxp[(size_t)N4 * DD];         // Wx^T packed fp16
__device__ float  g_bbp[N4];                      // bias packed fp32
__device__ __half g_Wp[(size_t)N4 * HH];          // Wh^T packed fp16
__device__ __half g_h[2][BB * HH];                // h state fp16
__device__ unsigned g_wcnt[2][8];                 // per-mg, per-unit-octet progress

// ---------------------------------------------------------------------------
// PTX helpers
// ---------------------------------------------------------------------------
__device__ __forceinline__ uint32_t smem_u32(const void* p) {
    uint32_t a;
    asm("{ .reg .u64 t; cvta.to.shared.u64 t, %1; cvt.u32.u64 %0, t; }" : "=r"(a) : "l"(p));
    return a;
}
__device__ __forceinline__ void cp_async16(uint32_t dst, const void* src) {
    asm volatile("cp.async.cg.shared.global [%0], [%1], 16;" :: "r"(dst), "l"(src));
}
#define CP_COMMIT() asm volatile("cp.async.commit_group;" ::: "memory")
#define CP_WAIT(n)  asm volatile("cp.async.wait_group %0;" :: "n"(n) : "memory")

__device__ __forceinline__ void ldmx4(uint32_t* r, uint32_t addr) {
    asm volatile("ldmatrix.sync.aligned.m8n8.x4.shared.b16 {%0,%1,%2,%3}, [%4];"
                 : "=r"(r[0]), "=r"(r[1]), "=r"(r[2]), "=r"(r[3]) : "r"(addr));
}
__device__ __forceinline__ void mma16816(float* d, const uint32_t* a, uint32_t b0, uint32_t b1) {
    asm volatile("mma.sync.aligned.m16n8k16.row.col.f32.f16.f16.f32 "
                 "{%0,%1,%2,%3}, {%4,%5,%6,%7}, {%8,%9}, {%0,%1,%2,%3};"
                 : "+f"(d[0]), "+f"(d[1]), "+f"(d[2]), "+f"(d[3])
                 : "r"(a[0]), "r"(a[1]), "r"(a[2]), "r"(a[3]), "r"(b0), "r"(b1));
}
__device__ __forceinline__ float sigf(float x) {
    return 1.0f / (1.0f + __expf(-x));
}

// Per-warp spin: lane0 acquires the counter, warp syncs (memory-ordered).
__device__ __forceinline__ void wait_cnt(const unsigned* cnt, unsigned target, int lane) {
    if (lane == 0) {
        unsigned v;
        do {
            asm volatile("ld.global.acquire.gpu.b32 %0, [%1];" : "=r"(v) : "l"(cnt));
        } while (v < target);
    }
    __syncwarp();
}

// ---------------------------------------------------------------------------
// Fused weight pack (all 4 gates) via 32x32 smem transpose.
// dst selected DEVICE-SIDE (GB300 ATS silently accepts host shadow addresses).
// ---------------------------------------------------------------------------
__global__ void prep_pack4(const float* __restrict__ s0, const float* __restrict__ s1,
                           const float* __restrict__ s2, const float* __restrict__ s3,
                           int Kdim, int is_wx)
{
    __shared__ __half tile[4][32][33];
    __half* __restrict__ dst = is_wx ? g_Wxp : g_Wp;
    const int k0 = blockIdx.x * 32;
    const int u0 = blockIdx.y * 32;
    const int tid = threadIdx.x;
    const int cx = tid & 31;
    const int ry = tid >> 5;
    const float* srcs[4] = { s0, s1, s2, s3 };

#pragma unroll
    for (int j = 0; j < 4; j++)
#pragma unroll
        for (int r = 0; r < 4; r++) {
            int ky = ry + r * 8;
            tile[j][ky][cx] = __float2half(srcs[j][(size_t)(k0 + ky) * HH + u0 + cx]);
        }
    __syncthreads();

#pragma unroll
    for (int j = 0; j < 4; j++)
#pragma unroll
        for (int r = 0; r < 4; r++) {
            int uy = ry + r * 8;
            int u = u0 + uy;
            int n = (u >> 3) * 32 + j * 8 + (u & 7);
            dst[(size_t)n * Kdim + k0 + cx] = tile[j][cx][uy];
        }
}

// Bias pack + h0 zero + counter reset.
__global__ void prep_misc(const float* __restrict__ bf, const float* __restrict__ bi,
                          const float* __restrict__ bg, const float* __restrict__ bo)
{
    int idx = blockIdx.x * blockDim.x + threadIdx.x;
    if (idx < HH) {
        int u = idx;
        float bv[4] = { bf[u], bi[u], bg[u], bo[u] };
#pragma unroll
        for (int j = 0; j < 4; j++)
            g_bbp[(u >> 3) * 32 + j * 8 + (u & 7)] = bv[j];
    }
    if (idx < BB * HH)
        g_h[0][idx] = __float2half(0.0f);
    if (idx < 16)
        g_wcnt[idx >> 3][idx & 7] = 0;
}

// x fp32 -> g_xA fp16, rows r = t*128 + b
__global__ void prep_x(const float* __restrict__ x)
{
    int idx = blockIdx.x * blockDim.x + threadIdx.x;
    int i4 = idx * 4;
    int r = i4 >> 8;
    int d = i4 & (DD - 1);
    int b = r & (BB - 1);
    int t = r >> 7;
    float4 v = *(const float4*)(x + ((size_t)b * TT + t) * DD + d);
    __half2 p0 = __floats2half2_rn(v.x, v.y);
    __half2 p1 = __floats2half2_rn(v.z, v.w);
    uint2 o = { *(uint32_t*)&p0, *(uint32_t*)&p1 };
    *(uint2*)(g_xA + (size_t)r * DD + d) = o;
}

// ---------------------------------------------------------------------------
// Load one 128-row x 64-col fp16 chunk (xg_mma tiles), swizzled.
// ---------------------------------------------------------------------------
__device__ __forceinline__ void load_tile128(uint32_t dst,
                                             const __half* __restrict__ src,
                                             int kb, int row_stride, int tid)
{
    const int s  = tid & 7;
    const int r0 = tid >> 3;
    const int ke = kb + s * 8;
#pragma unroll
    for (int p = 0; p < 4; p++) {
        int row = r0 + p * 32;
        uint32_t off = row * 128 + s * 16;
        uint32_t sw  = off ^ ((off >> 3) & 0x70);
        cp_async16(dst + sw, src + (size_t)row * row_stride + ke);
    }
}

// Load one 64-row x 64-col fp16 subtile (recurrence A), swizzled.
__device__ __forceinline__ void load_tile64(uint32_t dst,
                                            const __half* __restrict__ src,
                                            int kb, int tid)
{
    const int s  = tid & 7;
    const int row = tid >> 3;
#pragma unroll
    for (int p = 0; p < 2; p++) {
        int r = row + p * 32;
        uint32_t off = r * 128 + s * 16;
        uint32_t sw  = off ^ ((off >> 3) & 0x70);
        cp_async16(dst + sw, src + (size_t)r * HH + kb + s * 8);
    }
}

// ---------------------------------------------------------------------------
// xg = xA @ Wxp^T + bias (R12-proven kernel, unchanged)
// ---------------------------------------------------------------------------
__global__ void __launch_bounds__(256) xg_mma()
{
    extern __shared__ __align__(1024) char smem[];
    const uint32_t sb = smem_u32(smem);
    const int tid = threadIdx.x;
    const int w = tid >> 5;
    const int lane = tid & 31;
    const int N0 = blockIdx.x * 128;
    const int m0 = blockIdx.y * 128;

    const __half* Asrc = g_xA + (size_t)m0 * DD;
    const __half* Bsrc = g_Wxp + (size_t)N0 * DD;

    load_tile128(sb + 0, Asrc, 0, DD, tid);
    load_tile128(sb + 16384, Bsrc, 0, DD, tid);
    CP_COMMIT();

    const uint32_t a_row_off = (uint32_t)(w * 16 + (lane & 15)) * 128 + (lane >> 4) * 16;

    float acc[16][4];
#pragma unroll
    for (int i = 0; i < 16; i++)
#pragma unroll
        for (int q = 0; q < 4; q++) acc[i][q] = 0.0f;

    for (int ch = 0; ch < 4; ch++) {
        if (ch + 1 < 4) {
            uint32_t nb = sb + ((ch + 1) & 1) * 32768;
            load_tile128(nb, Asrc, (ch + 1) * 64, DD, tid);
            load_tile128(nb + 16384, Bsrc, (ch + 1) * 64, DD, tid);
            CP_COMMIT();
            CP_WAIT(1);
        } else {
            CP_WAIT(0);
        }
        __syncthreads();

        const uint32_t ab = sb + (ch & 1) * 32768;
        const uint32_t bb = ab + 16384;

#pragma unroll
        for (int k16 = 0; k16 < 4; k16++) {
            uint32_t a[4];
            {
                uint32_t off = a_row_off + (uint32_t)(k16 * 32);
                uint32_t sw = off ^ ((off >> 3) & 0x70);
                ldmx4(a, ab + sw);
            }
            uint32_t b0[4][4], b1[4][4];
#pragma unroll
            for (int g = 0; g < 4; g++) {
                uint32_t off0 = (uint32_t)(g * 32 + lane) * 128 + (uint32_t)(k16 * 32);
                uint32_t sw0 = off0 ^ ((off0 >> 3) & 0x70);
                ldmx4(b0[g], bb + sw0);
                uint32_t off1 = off0 + 16;
                uint32_t sw1 = off1 ^ ((off1 >> 3) & 0x70);
                ldmx4(b1[g], bb + sw1);
            }
#pragma unroll
            for (int g = 0; g < 4; g++)
#pragma unroll
                for (int m = 0; m < 4; m++)
                    mma16816(acc[g * 4 + m], a, b0[g][m], b1[g][m]);
        }
        __syncthreads();
    }

    __half* cs = (__half*)smem;
    const int r0 = w * 16 + (lane >> 2);
    const int e2 = (lane & 3) * 2;
#pragma unroll
    for (int g = 0; g < 4; g++) {
#pragma unroll
        for (int j = 0; j < 4; j++) {
            const int bidx = g * 4 + j;
            float2 bias = *(const float2*)(g_bbp + N0 + g * 32 + j * 8 + e2);
            const int cl0 = (g * 8 + e2) * 4 + j;
            const int cl1 = cl0 + 4;
            cs[r0 * XCROWH + cl0]       = __float2half(acc[bidx][0] + bias.x);
            cs[r0 * XCROWH + cl1]       = __float2half(acc[bidx][1] + bias.y);
            cs[(r0 + 8) * XCROWH + cl0] = __float2half(acc[bidx][2] + bias.x);
            cs[(r0 + 8) * XCROWH + cl1] = __float2half(acc[bidx][3] + bias.y);
        }
    }
    __syncthreads();

    for (int i = tid; i < 128 * 16; i += 256) {
        int row = i >> 4, seg = i & 15;
        uint4 v = *(uint4*)(cs + row * XCROWH + seg * 8);
        *(uint4*)(g_xg + (size_t)(m0 + row) * N4 + N0 + seg * 8) = v;
    }
}

// ---------------------------------------------------------------------------
// Persistent LSTM recurrence, fp16 MMA, 64x64 CTA tiles (R12 geometry).
// NO grid barrier: fine-grained producer/consumer sync. h unit u is produced
// by CTA ng=u/16 (same mg half); chunk ch (units 128ch..+127) waits on
// counter wcnt[mg][ch] >= 8*t (8 producers each incremented t times).
// Producers: syncthreads -> tid0 {threadfence; atomicAdd(wcnt[mg][ng>>3])}.
// WAR on double-buffered h is implied: finishing step t requires all chunk
// waits, hence all CTAs' step t-1 reads completed before our h writes.
// Chunk ch+3 load is issued AFTER compute of chunk ch (spin never blocks
// ready compute; >=2 chunk-computes of transfer overlap remain).
// ---------------------------------------------------------------------------
__global__ void __launch_bounds__(NTHR, 1) lstm_persist()
{
    extern __shared__ __align__(1024) char smem[];
    const uint32_t sb = smem_u32(smem);
    const int tid = threadIdx.x;
    const int w = tid >> 5;
    const int lane = tid & 31;
    const int mg = blockIdx.x >> 6;
    const int ng = blockIdx.x & 63;
    const int m_base = mg * 64;
    const int n0 = ng * 64;
    const int mw = w & 3;
    const int nw = w >> 2;

    // ---- one-time W tile load (64 x 1024 fp16); drains with first CP_WAIT ----
    {
        const __half* Wsrc = g_Wp + (size_t)n0 * HH;
        for (int i = tid; i < 8192; i += NTHR) {
            int n = i >> 7, s = i & 127;
            cp_async16(sb + S_WT + n * WROW + s * 16, Wsrc + (size_t)n * HH + s * 8);
        }
        CP_COMMIT();
    }

    const uint32_t wfrag = sb + S_WT + (uint32_t)(nw * 32 + lane) * WROW;
    const uint32_t a_row_off = (uint32_t)(mw * 16 + (lane & 15)) * 128 + (lane >> 4) * 16;

    const int row0 = m_base + mw * 16 + (lane >> 2);
    const int u0 = ng * 16 + nw * 8 + (lane & 3) * 2;
    const __half* xg_base0 = g_xg + (size_t)row0 * N4 + u0 * 4;
    const __half* xg_base1 = g_xg + (size_t)(row0 + 8) * N4 + u0 * 4;

    float creg[4] = { 0.0f, 0.0f, 0.0f, 0.0f };

    uint4 xq[2];
    xq[0] = *(const uint4*)(xg_base0);
    xq[1] = *(const uint4*)(xg_base1);

    const unsigned* const wc = g_wcnt[mg];
    unsigned* const myc = &g_wcnt[mg][ng >> 3];

    for (int t = 0; t < TT; t++) {
        const int par = t & 1;
        const __half* A = g_h[par] + (size_t)m_base * HH;
        const unsigned tgt = 8u * (unsigned)t;

        // prologue: chunks 0..2 (each gated by its producer counter)
#pragma unroll
        for (int pc = 0; pc < 3; pc++) {
            wait_cnt(&wc[pc], tgt, lane);
            uint32_t db = sb + S_ABUF + pc * ACH_SZ;
            load_tile64(db, A, pc * 128, tid);
            load_tile64(db + 8192, A, pc * 128 + 64, tid);
            CP_COMMIT();
        }

        float acc[4][4];
#pragma unroll
        for (int j = 0; j < 4; j++)
#pragma unroll
            for (int q = 0; q < 4; q++) acc[j][q] = 0.0f;

        for (int ch = 0; ch < 8; ch++) {
            if (ch <= 5)      { CP_WAIT(2); }
            else if (ch == 6) { CP_WAIT(1); }
            else              { CP_WAIT(0); }
            __syncthreads();

            const uint32_t ab = sb + S_ABUF + (ch & 3) * ACH_SZ;
#pragma unroll
            for (int sub = 0; sub < 2; sub++) {
                const uint32_t stb = ab + sub * 8192;
#pragma unroll
                for (int k16 = 0; k16 < 4; k16++) {
                    uint32_t ah[4];
                    uint32_t off = a_row_off + (uint32_t)(k16 * 32);
                    uint32_t sw = off ^ ((off >> 3) & 0x70);
                    ldmx4(ah, stb + sw);

                    const uint32_t kb = (uint32_t)(ch * 128 + sub * 64 + k16 * 16) * 2;
                    uint32_t b0[4], b1[4];
                    ldmx4(b0, wfrag + kb);
                    ldmx4(b1, wfrag + kb + 16);

#pragma unroll
                    for (int j = 0; j < 4; j++) mma16816(acc[j], ah, b0[j], b1[j]);
                }
            }

            // issue chunk ch+3 AFTER compute (spin never blocks ready work)
            if (ch + 3 < 8) {
                wait_cnt(&wc[ch + 3], tgt, lane);
                uint32_t db = sb + S_ABUF + ((ch + 3) & 3) * ACH_SZ;
                load_tile64(db, A, (ch + 3) * 128, tid);
                load_tile64(db + 8192, A, (ch + 3) * 128 + 64, tid);
                CP_COMMIT();
            }
        }

        // ---- epilogue: fused gates, c in regs, write h fp16 ----
        __half* hout = g_h[par ^ 1];
#pragma unroll
        for (int rr = 0; rr < 2; rr++) {
            float2 fi0 = __half22float2(*(__half2*)&xq[rr].x);
            float2 go0 = __half22float2(*(__half2*)&xq[rr].y);
            float2 fi1 = __half22float2(*(__half2*)&xq[rr].z);
            float2 go1 = __half22float2(*(__half2*)&xq[rr].w);

            float hv[2];
            {
                const int q = rr * 2;
                float fg = sigf(acc[0][q] + fi0.x);
                float ig = sigf(acc[1][q] + fi0.y);
                float gg = tanhf(acc[2][q] + go0.x);
                float og = sigf(acc[3][q] + go0.y);
                float cn = gg * ig + creg[q] * fg;
                creg[q] = cn;
                hv[0] = tanhf(cn) * og;
            }
            {
                const int q = rr * 2 + 1;
                float fg = sigf(acc[0][q] + fi1.x);
                float ig = sigf(acc[1][q] + fi1.y);
                float gg = tanhf(acc[2][q] + go1.x);
                float og = sigf(acc[3][q] + go1.y);
                float cn = gg * ig + creg[q] * fg;
                creg[q] = cn;
                hv[1] = tanhf(cn) * og;
            }
            const int row = row0 + rr * 8;
            *(__half2*)(hout + (size_t)row * HH + u0) = __floats2half2_rn(hv[0], hv[1]);
        }

        // prefetch next step's xq (independent of h)
        if (t + 1 < TT) {
            const size_t toff = (size_t)(t + 1) * BB * N4;
            xq[0] = *(const uint4*)(xg_base0 + toff);
            xq[1] = *(const uint4*)(xg_base1 + toff);
        }

        // ---- publish our h-octet for step t+1 consumers ----
        if (t < TT - 1) {
            __syncthreads();          // all threads' h writes done
            if (tid == 0) {
                __threadfence();      // gpu-scope release of the h writes
                atomicAdd(myc, 1u);
            }
        }
    }
}

// ---------------------------------------------------------------------------
// Final projection
// ---------------------------------------------------------------------------
__global__ void proj_kernel(const float* __restrict__ Wph,
                            const float* __restrict__ bp,
                            float* __restrict__ out)
{
    const int b = blockIdx.x;
    const int w = threadIdx.x >> 5;
    const int lane = threadIdx.x & 31;
    const __half* hr = g_h[0] + (size_t)b * HH;

    float s = 0.0f;
    for (int h = lane; h < HH; h += 32)
        s += __half2float(hr[h]) * Wph[(size_t)h * CC + w];
#pragma unroll
    for (int off = 16; off; off >>= 1)
        s += __shfl_xor_sync(0xffffffffu, s, off);
    if (lane == 0)
        out[b * CC + w] = s + bp[w];
}

// ---------------------------------------------------------------------------
// Launch
// ---------------------------------------------------------------------------
extern "C" void kernel_launch(void* const* d_in, const int* in_sizes, int n_in,
                              void* d_out, int out_size)
{
    const float* x   = (const float*)d_in[0];
    const float* Wfx = (const float*)d_in[1];
    const float* Wix = (const float*)d_in[2];
    const float* Wgx = (const float*)d_in[3];
    const float* Wox = (const float*)d_in[4];
    const float* Wfh = (const float*)d_in[5];
    const float* Wih = (const float*)d_in[6];
    const float* Wgh = (const float*)d_in[7];
    const float* Woh = (const float*)d_in[8];
    const float* bf  = (const float*)d_in[9];
    const float* bi  = (const float*)d_in[10];
    const float* bg  = (const float*)d_in[11];
    const float* bo  = (const float*)d_in[12];
    const float* Wph = (const float*)d_in[13];
    const float* bp  = (const float*)d_in[14];
    float* out = (float*)d_out;

    cudaFuncSetAttribute(lstm_persist, cudaFuncAttributeMaxDynamicSharedMemorySize,
                         STEP_SMEM);
    cudaFuncSetAttribute(xg_mma, cudaFuncAttributeMaxDynamicSharedMemorySize,
                         XG_SMEM);

    // 1) fused weight pack + bias/h0/counters
    prep_pack4<<<dim3(HH / 32, HH / 32), 256>>>(Wfh, Wih, Wgh, Woh, HH, 0);
    prep_pack4<<<dim3(DD / 32, HH / 32), 256>>>(Wfx, Wix, Wgx, Wox, DD, 1);
    prep_misc<<<(BB * HH + 255) / 256, 256>>>(bf, bi, bg, bo);

    // 2) x -> fp16
    prep_x<<<(TT * BB * DD / 4 + 255) / 256, 256>>>(x);

    // 3) input projections (fp16 MMA)
    xg_mma<<<dim3(N4 / 128, (TT * BB) / 128), 256, XG_SMEM>>>();

    // 4) persistent recurrence (fp16 MMA, fine-grained sync, no global barrier)
    lstm_persist<<<NCTA, NTHR, STEP_SMEM>>>();

    // 5) final projection
    proj_kernel<<<BB, CC * 32>>>(Wph, bp, out);
}

// round 15
// speedup vs baseline: 1.3847x; 1.3847x over previous
#include <cuda_runtime.h>
#include <cuda_fp16.h>
#include <math.h>
#include <stdint.h>

// Problem constants
#define BB 128      // batch
#define TT 256      // seq len
#define DD 256      // input dim
#define HH 1024     // hidden dim
#define CC 10       // classes
#define N4 4096     // 4*HH
#define NCTA 128    // persistent CTAs (one per SM)

// Step kernel constants (R12-proven geometry)
#define NTHR 256
#define WROW 2064                       // 1024 fp16 = 2048B + 16B pad
#define S_WT 0                          // W tile: 64 x WROW = 132096
#define S_ABUF (64 * WROW)              // 132096
#define ACH_SZ 16384                    // one A chunk: 64 rows x 128 fp16 (2 subtiles)
#define STEP_SMEM (S_ABUF + 4 * ACH_SZ) // 197632

// xg MMA kernel constants (R12-proven)
#define XG_SMEM 65536
#define XCROWH 136

// ---------------------------------------------------------------------------
// Device globals
// ---------------------------------------------------------------------------
__device__ __half g_xg[(size_t)TT * BB * N4];     // [t*128+b][n=u*4+j] fp16
__device__ __half g_xA[(size_t)TT * BB * DD];     // x rows r=t*128+b fp16
__device__ __half g_Wxp[(size_t)N4 * DD];         // Wx^T packed fp16
__device__ float  g_bbp[N4];                      // bias packed fp32
__device__ __half g_Wp[(size_t)N4 * HH];          // Wh^T packed fp16
__device__ __half g_h[2][BB * HH];                // h state fp16
__device__ unsigned g_barc[2];                    // per-mg-group grid barriers

// ---------------------------------------------------------------------------
// PTX helpers
// ---------------------------------------------------------------------------
__device__ __forceinline__ uint32_t smem_u32(const void* p) {
    uint32_t a;
    asm("{ .reg .u64 t; cvta.to.shared.u64 t, %1; cvt.u32.u64 %0, t; }" : "=r"(a) : "l"(p));
    return a;
}
__device__ __forceinline__ void cp_async16(uint32_t dst, const void* src) {
    asm volatile("cp.async.cg.shared.global [%0], [%1], 16;" :: "r"(dst), "l"(src));
}
#define CP_COMMIT() asm volatile("cp.async.commit_group;" ::: "memory")
#define CP_WAIT(n)  asm volatile("cp.async.wait_group %0;" :: "n"(n) : "memory")

__device__ __forceinline__ void ldmx4(uint32_t* r, uint32_t addr) {
    asm volatile("ldmatrix.sync.aligned.m8n8.x4.shared.b16 {%0,%1,%2,%3}, [%4];"
                 : "=r"(r[0]), "=r"(r[1]), "=r"(r[2]), "=r"(r[3]) : "r"(addr));
}
__device__ __forceinline__ void mma16816(float* d, const uint32_t* a, uint32_t b0, uint32_t b1) {
    asm volatile("mma.sync.aligned.m16n8k16.row.col.f32.f16.f16.f32 "
                 "{%0,%1,%2,%3}, {%4,%5,%6,%7}, {%8,%9}, {%0,%1,%2,%3};"
                 : "+f"(d[0]), "+f"(d[1]), "+f"(d[2]), "+f"(d[3])
                 : "r"(a[0]), "r"(a[1]), "r"(a[2]), "r"(a[3]), "r"(b0), "r"(b1));
}
__device__ __forceinline__ float sigf(float x) {
    return 1.0f / (1.0f + __expf(-x));
}

// ---------------------------------------------------------------------------
// Fused weight pack (all 4 gates) via 32x32 smem transpose.
// dst selected DEVICE-SIDE (GB300 ATS silently accepts host shadow addresses
// of __device__ arrays passed as kernel args — writes would go to host memory).
// dst[n(u,j)*Kdim + k] = srcj[k*HH + u],  n = (u/8)*32 + j*8 + (u%8)
// ---------------------------------------------------------------------------
__global__ void prep_pack4(const float* __restrict__ s0, const float* __restrict__ s1,
                           const float* __restrict__ s2, const float* __restrict__ s3,
                           int Kdim, int is_wx)
{
    __shared__ __half tile[4][32][33];
    __half* __restrict__ dst = is_wx ? g_Wxp : g_Wp;
    const int k0 = blockIdx.x * 32;
    const int u0 = blockIdx.y * 32;
    const int tid = threadIdx.x;
    const int cx = tid & 31;
    const int ry = tid >> 5;
    const float* srcs[4] = { s0, s1, s2, s3 };

#pragma unroll
    for (int j = 0; j < 4; j++)
#pragma unroll
        for (int r = 0; r < 4; r++) {
            int ky = ry + r * 8;
            tile[j][ky][cx] = __float2half(srcs[j][(size_t)(k0 + ky) * HH + u0 + cx]);
        }
    __syncthreads();

#pragma unroll
    for (int j = 0; j < 4; j++)
#pragma unroll
        for (int r = 0; r < 4; r++) {
            int uy = ry + r * 8;
            int u = u0 + uy;
            int n = (u >> 3) * 32 + j * 8 + (u & 7);
            dst[(size_t)n * Kdim + k0 + cx] = tile[j][cx][uy];
        }
}

// Bias pack + h0 zero + barrier reset.
__global__ void prep_misc(const float* __restrict__ bf, const float* __restrict__ bi,
                          const float* __restrict__ bg, const float* __restrict__ bo)
{
    int idx = blockIdx.x * blockDim.x + threadIdx.x;
    if (idx < HH) {
        int u = idx;
        float bv[4] = { bf[u], bi[u], bg[u], bo[u] };
#pragma unroll
        for (int j = 0; j < 4; j++)
            g_bbp[(u >> 3) * 32 + j * 8 + (u & 7)] = bv[j];
    }
    if (idx < BB * HH)
        g_h[0][idx] = __float2half(0.0f);
    if (idx < 2) g_barc[idx] = 0;
}

// x fp32 -> g_xA fp16, rows r = t*128 + b
__global__ void prep_x(const float* __restrict__ x)
{
    int idx = blockIdx.x * blockDim.x + threadIdx.x;
    int i4 = idx * 4;
    int r = i4 >> 8;
    int d = i4 & (DD - 1);
    int b = r & (BB - 1);
    int t = r >> 7;
    float4 v = *(const float4*)(x + ((size_t)b * TT + t) * DD + d);
    __half2 p0 = __floats2half2_rn(v.x, v.y);
    __half2 p1 = __floats2half2_rn(v.z, v.w);
    uint2 o = { *(uint32_t*)&p0, *(uint32_t*)&p1 };
    *(uint2*)(g_xA + (size_t)r * DD + d) = o;
}

// ---------------------------------------------------------------------------
// Load one 128-row x 64-col fp16 chunk (xg_mma tiles), swizzled.
// ---------------------------------------------------------------------------
__device__ __forceinline__ void load_tile128(uint32_t dst,
                                             const __half* __restrict__ src,
                                             int kb, int row_stride, int tid)
{
    const int s  = tid & 7;
    const int r0 = tid >> 3;
    const int ke = kb + s * 8;
#pragma unroll
    for (int p = 0; p < 4; p++) {
        int row = r0 + p * 32;
        uint32_t off = row * 128 + s * 16;
        uint32_t sw  = off ^ ((off >> 3) & 0x70);
        cp_async16(dst + sw, src + (size_t)row * row_stride + ke);
    }
}

// Load one 64-row x 64-col fp16 subtile (recurrence A), swizzled.
__device__ __forceinline__ void load_tile64(uint32_t dst,
                                            const __half* __restrict__ src,
                                            int kb, int tid)
{
    const int s  = tid & 7;
    const int row = tid >> 3;
#pragma unroll
    for (int p = 0; p < 2; p++) {
        int r = row + p * 32;
        uint32_t off = r * 128 + s * 16;
        uint32_t sw  = off ^ ((off >> 3) & 0x70);
        cp_async16(dst + sw, src + (size_t)r * HH + kb + s * 8);
    }
}

// ---------------------------------------------------------------------------
// xg = xA @ Wxp^T + bias (R12-proven kernel, unchanged)
// ---------------------------------------------------------------------------
__global__ void __launch_bounds__(256) xg_mma()
{
    extern __shared__ __align__(1024) char smem[];
    const uint32_t sb = smem_u32(smem);
    const int tid = threadIdx.x;
    const int w = tid >> 5;
    const int lane = tid & 31;
    const int N0 = blockIdx.x * 128;
    const int m0 = blockIdx.y * 128;

    const __half* Asrc = g_xA + (size_t)m0 * DD;
    const __half* Bsrc = g_Wxp + (size_t)N0 * DD;

    load_tile128(sb + 0, Asrc, 0, DD, tid);
    load_tile128(sb + 16384, Bsrc, 0, DD, tid);
    CP_COMMIT();

    const uint32_t a_row_off = (uint32_t)(w * 16 + (lane & 15)) * 128 + (lane >> 4) * 16;

    float acc[16][4];
#pragma unroll
    for (int i = 0; i < 16; i++)
#pragma unroll
        for (int q = 0; q < 4; q++) acc[i][q] = 0.0f;

    for (int ch = 0; ch < 4; ch++) {
        if (ch + 1 < 4) {
            uint32_t nb = sb + ((ch + 1) & 1) * 32768;
            load_tile128(nb, Asrc, (ch + 1) * 64, DD, tid);
            load_tile128(nb + 16384, Bsrc, (ch + 1) * 64, DD, tid);
            CP_COMMIT();
            CP_WAIT(1);
        } else {
            CP_WAIT(0);
        }
        __syncthreads();

        const uint32_t ab = sb + (ch & 1) * 32768;
        const uint32_t bb = ab + 16384;

#pragma unroll
        for (int k16 = 0; k16 < 4; k16++) {
            uint32_t a[4];
            {
                uint32_t off = a_row_off + (uint32_t)(k16 * 32);
                uint32_t sw = off ^ ((off >> 3) & 0x70);
                ldmx4(a, ab + sw);
            }
            uint32_t b0[4][4], b1[4][4];
#pragma unroll
            for (int g = 0; g < 4; g++) {
                uint32_t off0 = (uint32_t)(g * 32 + lane) * 128 + (uint32_t)(k16 * 32);
                uint32_t sw0 = off0 ^ ((off0 >> 3) & 0x70);
                ldmx4(b0[g], bb + sw0);
                uint32_t off1 = off0 + 16;
                uint32_t sw1 = off1 ^ ((off1 >> 3) & 0x70);
                ldmx4(b1[g], bb + sw1);
            }
#pragma unroll
            for (int g = 0; g < 4; g++)
#pragma unroll
                for (int m = 0; m < 4; m++)
                    mma16816(acc[g * 4 + m], a, b0[g][m], b1[g][m]);
        }
        __syncthreads();
    }

    __half* cs = (__half*)smem;
    const int r0 = w * 16 + (lane >> 2);
    const int e2 = (lane & 3) * 2;
#pragma unroll
    for (int g = 0; g < 4; g++) {
#pragma unroll
        for (int j = 0; j < 4; j++) {
            const int bidx = g * 4 + j;
            float2 bias = *(const float2*)(g_bbp + N0 + g * 32 + j * 8 + e2);
            const int cl0 = (g * 8 + e2) * 4 + j;
            const int cl1 = cl0 + 4;
            cs[r0 * XCROWH + cl0]       = __float2half(acc[bidx][0] + bias.x);
            cs[r0 * XCROWH + cl1]       = __float2half(acc[bidx][1] + bias.y);
            cs[(r0 + 8) * XCROWH + cl0] = __float2half(acc[bidx][2] + bias.x);
            cs[(r0 + 8) * XCROWH + cl1] = __float2half(acc[bidx][3] + bias.y);
        }
    }
    __syncthreads();

    for (int i = tid; i < 128 * 16; i += 256) {
        int row = i >> 4, seg = i & 15;
        uint4 v = *(uint4*)(cs + row * XCROWH + seg * 8);
        *(uint4*)(g_xg + (size_t)(m0 + row) * N4 + N0 + seg * 8) = v;
    }
}

// ---------------------------------------------------------------------------
// Persistent LSTM recurrence (EXACT R12 structure): fp16 MMA, 64x64 CTA
// tiles, 8 chunks of 128 K (2 subtiles each), 4-buffer pipeline distance 3,
// two independent 64-CTA barriers, xq prefetched one step ahead.
// Barrier arrive uses red.release.gpu (replaces threadfence+atomicAdd; the
// release on the increment orders prior h-writes; consumers ld.acquire.gpu).
// ---------------------------------------------------------------------------
__global__ void __launch_bounds__(NTHR, 1) lstm_persist()
{
    extern __shared__ __align__(1024) char smem[];
    const uint32_t sb = smem_u32(smem);
    const int tid = threadIdx.x;
    const int w = tid >> 5;
    const int lane = tid & 31;
    const int mg = blockIdx.x >> 6;       // 0..1 (independent batch half)
    const int ng = blockIdx.x & 63;       // 0..63
    const int m_base = mg * 64;
    const int n0 = ng * 64;
    const int mw = w & 3;
    const int nw = w >> 2;

    // ---- one-time W tile load (64 x 1024 fp16); drains with first CP_WAIT ----
    {
        const __half* Wsrc = g_Wp + (size_t)n0 * HH;
        for (int i = tid; i < 8192; i += NTHR) {
            int n = i >> 7, s = i & 127;
            cp_async16(sb + S_WT + n * WROW + s * 16, Wsrc + (size_t)n * HH + s * 8);
        }
        CP_COMMIT();
    }

    const uint32_t wfrag = sb + S_WT + (uint32_t)(nw * 32 + lane) * WROW;
    const uint32_t a_row_off = (uint32_t)(mw * 16 + (lane & 15)) * 128 + (lane >> 4) * 16;

    const int row0 = m_base + mw * 16 + (lane >> 2);
    const int u0 = ng * 16 + nw * 8 + (lane & 3) * 2;
    const __half* xg_base0 = g_xg + (size_t)row0 * N4 + u0 * 4;
    const __half* xg_base1 = g_xg + (size_t)(row0 + 8) * N4 + u0 * 4;

    float creg[4] = { 0.0f, 0.0f, 0.0f, 0.0f };

    uint4 xq[2];
    xq[0] = *(const uint4*)(xg_base0);
    xq[1] = *(const uint4*)(xg_base1);

    unsigned* const barp = &g_barc[mg];

    for (int t = 0; t < TT; t++) {
        const int par = t & 1;
        const __half* A = g_h[par] + (size_t)m_base * HH;

        // pipeline prologue: chunks 0..2 (each 128 K = 2 subtiles)
#pragma unroll
        for (int pc = 0; pc < 3; pc++) {
            uint32_t db = sb + S_ABUF + pc * ACH_SZ;
            load_tile64(db, A, pc * 128, tid);
            load_tile64(db + 8192, A, pc * 128 + 64, tid);
            CP_COMMIT();
        }

        float acc[4][4];
#pragma unroll
        for (int j = 0; j < 4; j++)
#pragma unroll
            for (int q = 0; q < 4; q++) acc[j][q] = 0.0f;

        for (int ch = 0; ch < 8; ch++) {
            if (ch <= 5)      { CP_WAIT(2); }
            else if (ch == 6) { CP_WAIT(1); }
            else              { CP_WAIT(0); }
            __syncthreads();

            if (ch + 3 < 8) {
                uint32_t db = sb + S_ABUF + ((ch + 3) & 3) * ACH_SZ;
                load_tile64(db, A, (ch + 3) * 128, tid);
                load_tile64(db + 8192, A, (ch + 3) * 128 + 64, tid);
                CP_COMMIT();
            }

            const uint32_t ab = sb + S_ABUF + (ch & 3) * ACH_SZ;
#pragma unroll
            for (int sub = 0; sub < 2; sub++) {
                const uint32_t stb = ab + sub * 8192;
#pragma unroll
                for (int k16 = 0; k16 < 4; k16++) {
                    uint32_t ah[4];
                    uint32_t off = a_row_off + (uint32_t)(k16 * 32);
                    uint32_t sw = off ^ ((off >> 3) & 0x70);
                    ldmx4(ah, stb + sw);

                    const uint32_t kb = (uint32_t)(ch * 128 + sub * 64 + k16 * 16) * 2;
                    uint32_t b0[4], b1[4];
                    ldmx4(b0, wfrag + kb);
                    ldmx4(b1, wfrag + kb + 16);

#pragma unroll
                    for (int j = 0; j < 4; j++) mma16816(acc[j], ah, b0[j], b1[j]);
                }
            }
        }

        // ---- epilogue: fused gates, c in regs, write h fp16 ----
        __half* hout = g_h[par ^ 1];
#pragma unroll
        for (int rr = 0; rr < 2; rr++) {
            float2 fi0 = __half22float2(*(__half2*)&xq[rr].x);
            float2 go0 = __half22float2(*(__half2*)&xq[rr].y);
            float2 fi1 = __half22float2(*(__half2*)&xq[rr].z);
            float2 go1 = __half22float2(*(__half2*)&xq[rr].w);

            float hv[2];
            {
                const int q = rr * 2;
                float fg = sigf(acc[0][q] + fi0.x);
                float ig = sigf(acc[1][q] + fi0.y);
                float gg = tanhf(acc[2][q] + go0.x);
                float og = sigf(acc[3][q] + go0.y);
                float cn = gg * ig + creg[q] * fg;
                creg[q] = cn;
                hv[0] = tanhf(cn) * og;
            }
            {
                const int q = rr * 2 + 1;
                float fg = sigf(acc[0][q] + fi1.x);
                float ig = sigf(acc[1][q] + fi1.y);
                float gg = tanhf(acc[2][q] + go1.x);
                float og = sigf(acc[3][q] + go1.y);
                float cn = gg * ig + creg[q] * fg;
                creg[q] = cn;
                hv[1] = tanhf(cn) * og;
            }
            const int row = row0 + rr * 8;
            *(__half2*)(hout + (size_t)row * HH + u0) = __floats2half2_rn(hv[0], hv[1]);
        }

        // prefetch next step's xq (independent of h; hides DRAM latency)
        if (t + 1 < TT) {
            const size_t toff = (size_t)(t + 1) * BB * N4;
            xq[0] = *(const uint4*)(xg_base0 + toff);
            xq[1] = *(const uint4*)(xg_base1 + toff);
        }

        // ---- per-group grid barrier (64 CTAs; release-arrive by tid0) ----
        if (t < TT - 1) {
            __syncthreads();          // all h-writes of this CTA done
            if (tid == 0) {
                asm volatile("red.release.gpu.global.add.u32 [%0], 1;"
                             :: "l"(barp) : "memory");
                const unsigned target = 64u * (unsigned)(t + 1);
                unsigned v;
                do {
                    asm volatile("ld.global.acquire.gpu.b32 %0, [%1];"
                                 : "=r"(v) : "l"(barp));
                } while (v < target);
            }
            __syncthreads();
        }
    }
}

// ---------------------------------------------------------------------------
// Final projection
// ---------------------------------------------------------------------------
__global__ void proj_kernel(const float* __restrict__ Wph,
                            const float* __restrict__ bp,
                            float* __restrict__ out)
{
    const int b = blockIdx.x;
    const int w = threadIdx.x >> 5;
    const int lane = threadIdx.x & 31;
    const __half* hr = g_h[0] + (size_t)b * HH;

    float s = 0.0f;
    for (int h = lane; h < HH; h += 32)
        s += __half2float(hr[h]) * Wph[(size_t)h * CC + w];
#pragma unroll
    for (int off = 16; off; off >>= 1)
        s += __shfl_xor_sync(0xffffffffu, s, off);
    if (lane == 0)
        out[b * CC + w] = s + bp[w];
}

// ---------------------------------------------------------------------------
// Launch
// ---------------------------------------------------------------------------
extern "C" void kernel_launch(void* const* d_in, const int* in_sizes, int n_in,
                              void* d_out, int out_size)
{
    const float* x   = (const float*)d_in[0];
    const float* Wfx = (const float*)d_in[1];
    const float* Wix = (const float*)d_in[2];
    const float* Wgx = (const float*)d_in[3];
    const float* Wox = (const float*)d_in[4];
    const float* Wfh = (const float*)d_in[5];
    const float* Wih = (const float*)d_in[6];
    const float* Wgh = (const float*)d_in[7];
    const float* Woh = (const float*)d_in[8];
    const float* bf  = (const float*)d_in[9];
    const float* bi  = (const float*)d_in[10];
    const float* bg  = (const float*)d_in[11];
    const float* bo  = (const float*)d_in[12];
    const float* Wph = (const float*)d_in[13];
    const float* bp  = (const float*)d_in[14];
    float* out = (float*)d_out;

    cudaFuncSetAttribute(lstm_persist, cudaFuncAttributeMaxDynamicSharedMemorySize,
                         STEP_SMEM);
    cudaFuncSetAttribute(xg_mma, cudaFuncAttributeMaxDynamicSharedMemorySize,
                         XG_SMEM);

    // 1) fused weight pack + bias/h0/barriers
    prep_pack4<<<dim3(HH / 32, HH / 32), 256>>>(Wfh, Wih, Wgh, Woh, HH, 0);
    prep_pack4<<<dim3(DD / 32, HH / 32), 256>>>(Wfx, Wix, Wgx, Wox, DD, 1);
    prep_misc<<<(BB * HH + 255) / 256, 256>>>(bf, bi, bg, bo);

    // 2) x -> fp16
    prep_x<<<(TT * BB * DD / 4 + 255) / 256, 256>>>(x);

    // 3) input projections (fp16 MMA)
    xg_mma<<<dim3(N4 / 128, (TT * BB) / 128), 256, XG_SMEM>>>();

    // 4) persistent recurrence (R12 structure, release-atomic barrier)
    lstm_persist<<<NCTA, NTHR, STEP_SMEM>>>();

    // 5) final projection
    proj_kernel<<<BB, CC * 32>>>(Wph, bp, out);
}